// round 6
// baseline (speedup 1.0000x reference)
#include <cuda_runtime.h>
#include <cstddef>

// Math collapse (B=1, L=2048, DIM=16, HEADS=DIM_HEAD=1):
// softmax over size-1 axis == 1  =>  out[i, j, d] = v[i]*W_out[d] + b_out[d],
// v[i] = dot(x[i,:], W_qkv[2,:]).  Output (1,2048,2048,16) fp32 = 268 MB.
//
// Bottleneck analysis (R2/R4/R5): all stores traverse L2; effective rate
// 6.6 TB/s == LTS chip cap (~6300 B/cyc, path-independent). This round:
// 1024 CTAs x 2 rows (uniform single wave, no partial tail) with the two
// rows' store streams interleaved (2x per-thread store MLP).

#define L_TOKENS  2048
#define DIM_IN    16
#define ROW_F4    (L_TOKENS * DIM_IN / 4)   // 8192 float4 per i-row (128 KB)
#define THREADS   256
#define GRID_CTAS (L_TOKENS / 2)            // 1024 CTAs, 2 rows each

__global__ __launch_bounds__(THREADS, 8)
void attn_broadcast2_kernel(const float* __restrict__ x,
                            const float* __restrict__ Wqkv,   // (3,16); v-row at +32
                            const float* __restrict__ Wout,   // (16,1)
                            const float* __restrict__ bout,   // (16,)
                            float4* __restrict__ out)
{
    const int i0  = blockIdx.x * 2;         // rows i0 and i0+1
    const int tid = threadIdx.x;
    const int w   = tid >> 5;
    const int lane = tid & 31;

    __shared__ float4 pat[2][4];             // 16-float pattern per row

    if (w < 2) {
        const int row = i0 + w;
        // v[row] = dot(x[row, 0:16], Wqkv[2, 0:16])
        float prod = 0.0f;
        if (lane < 16)
            prod = x[row * DIM_IN + lane] * Wqkv[32 + lane];
        #pragma unroll
        for (int off = 8; off > 0; off >>= 1)
            prod += __shfl_down_sync(0xffffffffu, prod, off);
        float v = __shfl_sync(0xffffffffu, prod, 0);
        if (lane < 16)
            reinterpret_cast<float*>(pat[w])[lane] = v * Wout[lane] + bout[lane];
    }
    __syncthreads();

    // (k & 3) == (tid & 3) every iteration (THREADS % 4 == 0): each thread
    // re-stores two register-held float4s, perfectly coalesced 128B lines.
    const float4 v0 = pat[0][tid & 3];
    const float4 v1 = pat[1][tid & 3];
    const size_t b0 = (size_t)i0 * ROW_F4;
    const size_t b1 = b0 + ROW_F4;

    // Interleaved dual-row streaming stores: 2 independent STG.128 per
    // iteration -> doubled outstanding-store MLP, two open DRAM regions.
    #pragma unroll 8
    for (int k = tid; k < ROW_F4; k += THREADS) {
        __stcs(out + b0 + k, v0);
        __stcs(out + b1 + k, v1);
    }
}

extern "C" void kernel_launch(void* const* d_in, const int* in_sizes, int n_in,
                              void* d_out, int out_size)
{
    const float* x    = (const float*)d_in[0];   // (1, 2048, 16)
    const float* Wqkv = (const float*)d_in[1];   // (3, 16)
    const float* Wout = (const float*)d_in[2];   // (16, 1)
    const float* bout = (const float*)d_in[3];   // (16,)
    float4* out = (float4*)d_out;                // (1, 2048, 2048, 16) fp32

    attn_broadcast2_kernel<<<GRID_CTAS, THREADS>>>(x, Wqkv, Wout, bout, out);
}

// round 7
// speedup vs baseline: 1.0471x; 1.0471x over previous
#include <cuda_runtime.h>
#include <cstddef>

// Math collapse (B=1, L=2048, DIM=16, HEADS=DIM_HEAD=1):
// softmax over size-1 axis == 1  =>  out[i, j, d] = v[i]*W_out[d] + b_out[d],
// v[i] = dot(x[i,:], W_qkv[2,:]).  Output (1,2048,2048,16) fp32 = 268 MB.
//
// Roofline status (R2/R4/R5/R6): every structure lands at 40.3-41.6us kernel
// = 6.5-6.7 TB/s effective store rate == LTS chip cap (path-independent;
// stores cannot bypass L2). This round strips the last non-store costs from
// the best (R2) structure: no shared memory, no __syncthreads — each thread
// computes the 16-float pattern redundantly in registers (L1-broadcast
// loads, once per CTA), then streams its float4 lane.

#define L_TOKENS  2048
#define DIM_IN    16
#define ROW_F4    (L_TOKENS * DIM_IN / 4)   // 8192 float4 per i-row (128 KB)
#define THREADS   256

__global__ __launch_bounds__(THREADS, 8)
void attn_broadcast_reg_kernel(const float* __restrict__ x,
                               const float* __restrict__ Wqkv,   // (3,16); v-row at +32
                               const float* __restrict__ Wout,   // (16,1)
                               const float* __restrict__ bout,   // (16,)
                               float4* __restrict__ out)
{
    const int i   = blockIdx.x;
    const int tid = threadIdx.x;

    // v[i] = dot(x[i, 0:16], Wqkv[2, 0:16]) — computed by every thread from
    // L1-broadcast loads (same addresses warp-wide -> single wavefront each).
    const float4* xr = (const float4*)(x + i * DIM_IN);
    const float4* wv = (const float4*)(Wqkv + 2 * DIM_IN);
    float v = 0.0f;
    #pragma unroll
    for (int q = 0; q < 4; ++q) {
        float4 a = xr[q], b = wv[q];
        v = fmaf(a.x, b.x, v); v = fmaf(a.y, b.y, v);
        v = fmaf(a.z, b.z, v); v = fmaf(a.w, b.w, v);
    }

    // This thread's float4 lane of the 16-float pattern. Since THREADS % 4
    // == 0 and ROW_F4 % 4 == 0, (k & 3) == (tid & 3) for every store.
    const int d_base = (tid & 3) * 4;
    const float4 wo = *(const float4*)(Wout + d_base);
    const float4 bo = *(const float4*)(bout + d_base);
    const float4 val = make_float4(fmaf(v, wo.x, bo.x), fmaf(v, wo.y, bo.y),
                                   fmaf(v, wo.z, bo.z), fmaf(v, wo.w, bo.w));

    const size_t base = (size_t)i * ROW_F4;

    // Pure streaming store loop: one register-held float4 per thread,
    // perfectly coalesced 128B lines, evict-first (no L2 reuse exists).
    #pragma unroll 8
    for (int k = tid; k < ROW_F4; k += THREADS)
        __stcs(out + base + k, val);
}

extern "C" void kernel_launch(void* const* d_in, const int* in_sizes, int n_in,
                              void* d_out, int out_size)
{
    const float* x    = (const float*)d_in[0];   // (1, 2048, 16)
    const float* Wqkv = (const float*)d_in[1];   // (3, 16)
    const float* Wout = (const float*)d_in[2];   // (16, 1)
    const float* bout = (const float*)d_in[3];   // (16,)
    float4* out = (float4*)d_out;                // (1, 2048, 2048, 16) fp32

    attn_broadcast_reg_kernel<<<L_TOKENS, THREADS>>>(x, Wqkv, Wout, bout, out);
}